// round 3
// baseline (speedup 1.0000x reference)
#include <cuda_runtime.h>
#include <cuda_bf16.h>
#include <math.h>

// ---------------------------------------------------------------------------
// 3x exact top-K over columns of A (N x 2), (value desc, index asc) = lax.top_k.
// 4-launch pipeline:
//   H: chip-wide 16384-bin histograms of fkey(v), fkey(vo); last block picks
//      threshold bins for all 3 selections (top-K v, bottom-K v, top-K vo)
//   C: chip-wide candidate compaction (warp-aggregated appends)
//   S: 3 blocks bitonic-sort <=4096 candidates each, emit sorted indices,
//      then ZERO all selection state for the next graph replay
//   G: gather h rows, 512->2 GEMV (W in smem), softmax(2), write outputs
// State is zero at module load; S re-zeroes at the end of every call, so each
// call (correctness run and every replay) sees identical initial state.
// Output (float32, 15K): [0,3K) labels | [3K,9K) logits | [9K,15K) softmax
// ---------------------------------------------------------------------------

#define NBINS   16384
#define CAP     4096
#define KMAX    2048
#define SCAN_T  256
#define BPT     (NBINS / SCAN_T)   // 64 bins per thread in pick

__device__ unsigned            g_hist[2][NBINS];   // [0]: fkey(v)  [1]: fkey(vo)
__device__ unsigned            g_done;
__device__ unsigned            g_bin[3];           // lo0 (>=), hi1 (<=), lo2 (>=)
__device__ int                 g_cnt[3];
__device__ unsigned long long  g_cand[3][CAP];
__device__ int                 g_idx[3 * KMAX];

__device__ __forceinline__ unsigned fkey(float f) {
    unsigned u = __float_as_uint(f);
    return (u & 0x80000000u) ? ~u : (u | 0x80000000u);   // monotonic; fkey(-f)==~fkey(f)
}

__device__ __forceinline__ void agg_add(unsigned* hist, unsigned bin) {
    unsigned act = __activemask();
    unsigned mm  = __match_any_sync(act, bin);
    if ((__ffs(mm) - 1) == (int)(threadIdx.x & 31))
        atomicAdd(&hist[bin], __popc(mm));
}

// ---- H: histogram + fused threshold pick (last block) ----------------------
__global__ __launch_bounds__(SCAN_T)
void hist_kernel(const float2* __restrict__ A2, const int* __restrict__ bag,
                 int N, int K) {
    const int tid = threadIdx.x;
    const int i = blockIdx.x * SCAN_T + tid;
    const int bg = __ldg(bag);

    if (i < N) {
        float2 a = A2[i];
        float v  = bg ? a.y : a.x;
        float vo = bg ? a.x : a.y;
        agg_add(g_hist[0], fkey(v)  >> 18);
        agg_add(g_hist[1], fkey(vo) >> 18);
    }

    // last-block-done: pick thresholds
    __shared__ bool amLast;
    __threadfence();
    if (tid == 0) amLast = (atomicAdd(&g_done, 1u) == (unsigned)gridDim.x - 1u);
    __syncthreads();
    if (!amLast) return;

    __shared__ unsigned s[SCAN_T];
    const unsigned uK = (unsigned)K;

    #pragma unroll
    for (int hh = 0; hh < 2; hh++) {
        const unsigned* hist = g_hist[hh];
        unsigned part = 0;
        #pragma unroll 8
        for (int j = 0; j < BPT; j++) part += __ldcg(&hist[tid * BPT + j]);
        s[tid] = part;
        __syncthreads();
        for (int off = 1; off < SCAN_T; off <<= 1) {     // inclusive scan
            unsigned v = (tid >= off) ? s[tid - off] : 0u;
            __syncthreads();
            s[tid] += v;
            __syncthreads();
        }
        unsigned asc   = s[tid];
        unsigned total = s[SCAN_T - 1];

        // bottom-K (only hist0 -> sel1): ascending walk
        if (hh == 0) {
            unsigned before = asc - part;
            if (before < uK && asc >= uK) {
                int kk = K - (int)before;
                for (int j = 0; j < BPT; j++) {
                    int b = tid * BPT + j;
                    kk -= (int)__ldcg(&hist[b]);
                    if (kk <= 0) { g_bin[1] = (unsigned)b; break; }
                }
            }
        }
        // top-K: descending walk
        {
            unsigned before = total - asc;
            if (before < uK && before + part >= uK) {
                int kk = K - (int)before;
                for (int j = BPT - 1; j >= 0; j--) {
                    int b = tid * BPT + j;
                    kk -= (int)__ldcg(&hist[b]);
                    if (kk <= 0) { g_bin[hh == 0 ? 0 : 2] = (unsigned)b; break; }
                }
            }
        }
        __syncthreads();
    }
}

// ---- C: warp-aggregated candidate compaction --------------------------------
__device__ __forceinline__ void append_warp(int sel, bool pred, unsigned long long key) {
    unsigned m = __ballot_sync(0xFFFFFFFFu, pred);
    if (!m) return;
    int leader = __ffs(m) - 1;
    int lane = threadIdx.x & 31;
    int base = 0;
    if (lane == leader) base = atomicAdd(&g_cnt[sel], __popc(m));
    base = __shfl_sync(0xFFFFFFFFu, base, leader);
    if (pred) {
        int p = base + __popc(m & ((1u << lane) - 1u));
        if (p < CAP) g_cand[sel][p] = key;
    }
}

__global__ __launch_bounds__(256)
void compact_kernel(const float2* __restrict__ A2, const int* __restrict__ bag,
                    int N) {
    const int i = blockIdx.x * 256 + threadIdx.x;
    const int bg = __ldg(bag);
    const unsigned lo0 = __ldcg(&g_bin[0]);
    const unsigned hi1 = __ldcg(&g_bin[1]);
    const unsigned lo2 = __ldcg(&g_bin[2]);

    const bool valid = (i < N);
    float2 a = valid ? A2[i] : make_float2(0.f, 0.f);
    float v  = bg ? a.y : a.x;
    float vo = bg ? a.x : a.y;
    unsigned k0 = fkey(v), k2 = fkey(vo);
    unsigned long long il = (unsigned)(~(unsigned)i);

    append_warp(0, valid && ((k0 >> 18) >= lo0), ((unsigned long long)k0    << 32) | il);
    append_warp(1, valid && ((k0 >> 18) <= hi1), ((unsigned long long)(~k0) << 32) | il);
    append_warp(2, valid && ((k2 >> 18) >= lo2), ((unsigned long long)k2    << 32) | il);
}

// ---- S: per-selection bitonic sort + state zeroing for next replay ----------
__global__ __launch_bounds__(1024)
void sort_kernel(int K) {
    const int sel = blockIdx.x, tid = threadIdx.x;
    __shared__ unsigned long long keys[CAP];

    int cnt = g_cnt[sel]; if (cnt > CAP) cnt = CAP;
    for (int j = tid; j < CAP; j += 1024)
        keys[j] = (j < cnt) ? g_cand[sel][j] : 0ull;
    __syncthreads();

    for (unsigned size = 2; size <= CAP; size <<= 1) {
        for (unsigned stride = size >> 1; stride > 0; stride >>= 1) {
            #pragma unroll 2
            for (int p = tid; p < CAP / 2; p += 1024) {
                unsigned lo = p & (stride - 1);
                unsigned i  = ((unsigned)(p - lo) << 1) | lo;
                unsigned j  = i + stride;
                bool up = ((i & size) == 0);
                unsigned long long a = keys[i], c = keys[j];
                if (up ? (a > c) : (a < c)) { keys[i] = c; keys[j] = a; }
            }
            __syncthreads();
        }
    }

    for (int j = tid; j < K; j += 1024) {
        unsigned long long key = keys[CAP - 1 - j];
        g_idx[sel * K + j] = (int)(~(unsigned)(key & 0xFFFFFFFFull));
    }

    // zero state for next call (each block takes a third of the histograms)
    unsigned* hp = (unsigned*)g_hist;
    const int total = 2 * NBINS;
    const int chunk = (total + 2) / 3;
    const int s0 = sel * chunk;
    const int e0 = (s0 + chunk < total) ? s0 + chunk : total;
    for (int i = s0 + tid; i < e0; i += 1024) hp[i] = 0u;
    if (tid == 0) {
        g_cnt[sel] = 0;
        if (sel == 0) g_done = 0u;
    }
}

// ---- G: gather + GEMV(512->2) + softmax; 2 rows per warp --------------------
__global__ void gemv_softmax_kernel(const float* __restrict__ h,
                                    const float* __restrict__ W,
                                    const float* __restrict__ b,
                                    float* __restrict__ out,
                                    int D, int K) {
    extern __shared__ float ws[];   // D*2 floats, W[d*2+c]
    const int tid = threadIdx.x;
    for (int j = tid; j < D * 2; j += blockDim.x) ws[j] = W[j];
    __syncthreads();

    const int warp = tid >> 5, lane = tid & 31;
    const int rbase = (blockIdx.x * (blockDim.x >> 5) + warp) * 2;
    const int total = 3 * K;
    if (rbase >= total) return;

    const bool two = (rbase + 1 < total);
    const int ia = g_idx[rbase];
    const int ib = two ? g_idx[rbase + 1] : ia;
    const float4* pa = (const float4*)(h + (size_t)ia * D);
    const float4* pb = (const float4*)(h + (size_t)ib * D);

    float a0 = 0.f, a1 = 0.f, b0 = 0.f, b1 = 0.f;
    const int nq = D >> 2;
    for (int t = lane; t < nq; t += 32) {
        float4 va = pa[t];
        float4 vb = pb[t];
        int j = t << 3;
        a0 = fmaf(va.x, ws[j + 0], a0);  a1 = fmaf(va.x, ws[j + 1], a1);
        b0 = fmaf(vb.x, ws[j + 0], b0);  b1 = fmaf(vb.x, ws[j + 1], b1);
        a0 = fmaf(va.y, ws[j + 2], a0);  a1 = fmaf(va.y, ws[j + 3], a1);
        b0 = fmaf(vb.y, ws[j + 2], b0);  b1 = fmaf(vb.y, ws[j + 3], b1);
        a0 = fmaf(va.z, ws[j + 4], a0);  a1 = fmaf(va.z, ws[j + 5], a1);
        b0 = fmaf(vb.z, ws[j + 4], b0);  b1 = fmaf(vb.z, ws[j + 5], b1);
        a0 = fmaf(va.w, ws[j + 6], a0);  a1 = fmaf(va.w, ws[j + 7], a1);
        b0 = fmaf(vb.w, ws[j + 6], b0);  b1 = fmaf(vb.w, ws[j + 7], b1);
    }
    #pragma unroll
    for (int o = 16; o; o >>= 1) {
        a0 += __shfl_down_sync(0xFFFFFFFFu, a0, o);
        a1 += __shfl_down_sync(0xFFFFFFFFu, a1, o);
        b0 += __shfl_down_sync(0xFFFFFFFFu, b0, o);
        b1 += __shfl_down_sync(0xFFFFFFFFu, b1, o);
    }

    if (lane == 0) {
        float bb0 = b[0], bb1 = b[1];
        {
            int r = rbase;
            float z0 = a0 + bb0, z1 = a1 + bb1;
            float m = fmaxf(z0, z1);
            float e0 = expf(z0 - m), e1 = expf(z1 - m);
            float inv = 1.0f / (e0 + e1);
            out[r] = (r < K) ? 1.0f : 0.0f;
            out[3 * K + r * 2 + 0] = z0;
            out[3 * K + r * 2 + 1] = z1;
            out[9 * K + r * 2 + 0] = e0 * inv;
            out[9 * K + r * 2 + 1] = e1 * inv;
        }
        if (two) {
            int r = rbase + 1;
            float z0 = b0 + bb0, z1 = b1 + bb1;
            float m = fmaxf(z0, z1);
            float e0 = expf(z0 - m), e1 = expf(z1 - m);
            float inv = 1.0f / (e0 + e1);
            out[r] = (r < K) ? 1.0f : 0.0f;
            out[3 * K + r * 2 + 0] = z0;
            out[3 * K + r * 2 + 1] = z1;
            out[9 * K + r * 2 + 0] = e0 * inv;
            out[9 * K + r * 2 + 1] = e1 * inv;
        }
    }
}

extern "C" void kernel_launch(void* const* d_in, const int* in_sizes, int n_in,
                              void* d_out, int out_size) {
    const float* h = (const float*)d_in[0];   // (N,1,D)
    const float* A = (const float*)d_in[1];   // (N,1,2)
    const float* W = (const float*)d_in[2];   // (D,2)
    const float* b = (const float*)d_in[3];   // (2,)
    const int* bag = (const int*)d_in[4];

    const int N = in_sizes[1] / 2;
    const int D = in_sizes[0] / N;
    int K = (int)(0.02 * (double)N);
    if (K == 0) K = 8;
    if (K > KMAX) K = KMAX;

    const float2* A2 = (const float2*)A;
    const int grid = (N + SCAN_T - 1) / SCAN_T;

    hist_kernel<<<grid, SCAN_T>>>(A2, bag, N, K);
    compact_kernel<<<grid, 256>>>(A2, bag, N);
    sort_kernel<<<3, 1024>>>(K);

    const int rows = 3 * K;
    const int blocks = (rows + 15) / 16;
    const size_t smem = (size_t)(D * 2) * sizeof(float);
    gemv_softmax_kernel<<<blocks, 256, smem>>>(h, W, b, (float*)d_out, D, K);
}

// round 4
// speedup vs baseline: 1.4744x; 1.4744x over previous
#include <cuda_runtime.h>
#include <cuda_bf16.h>
#include <math.h>

// ---------------------------------------------------------------------------
// 3x exact top-K over columns of A (N x 2), (value desc, index asc) = lax.top_k.
// 5-launch pipeline (NO device-wide fences anywhere):
//   H: chip-wide 16384-bin histograms of fkey(v), fkey(vo)
//   P: 2 blocks pick threshold bins (sel0 top-K v, sel1 bottom-K v, sel2 top-K vo)
//   C: chip-wide candidate compaction (warp-aggregated appends), 1 elem/thread
//   S: 3 blocks bitonic-sort <=4096 candidates, emit indices, then zero state
//   G: gather h rows, 512->2 GEMV (W in smem), softmax(2), write outputs
// State is zero at module load; S re-zeroes at end of every call => every call
// (correctness + each graph replay) sees identical initial state.
// Output (float32, 15K): [0,3K) labels | [3K,9K) logits | [9K,15K) softmax
// ---------------------------------------------------------------------------

#define NBINS   16384
#define CAP     4096
#define KMAX    2048
#define PICK_T  1024
#define PBPT    (NBINS / PICK_T)    // 16 bins/thread in pick

__device__ unsigned            g_hist[2][NBINS];   // [0]: fkey(v)  [1]: fkey(vo)
__device__ unsigned            g_bin[3];           // lo0 (>=), hi1 (<=), lo2 (>=)
__device__ int                 g_cnt[3];
__device__ unsigned long long  g_cand[3][CAP];
__device__ int                 g_idx[3 * KMAX];

__device__ __forceinline__ unsigned fkey(float f) {
    unsigned u = __float_as_uint(f);
    return (u & 0x80000000u) ? ~u : (u | 0x80000000u);   // monotonic
}

__device__ __forceinline__ void agg_add(unsigned* hist, unsigned bin) {
    unsigned act = __activemask();
    unsigned mm  = __match_any_sync(act, bin);
    if ((__ffs(mm) - 1) == (int)(threadIdx.x & 31))
        atomicAdd(&hist[bin], __popc(mm));
}

// ---- H: chip-wide histograms ------------------------------------------------
__global__ __launch_bounds__(256)
void hist_kernel(const float2* __restrict__ A2, const int* __restrict__ bag, int N) {
    const int bg = __ldg(bag);
    const int stride = gridDim.x * 256;
    for (int i = blockIdx.x * 256 + threadIdx.x; i < N; i += stride) {
        float2 a = A2[i];
        float v  = bg ? a.y : a.x;
        float vo = bg ? a.x : a.y;
        agg_add(g_hist[0], fkey(v)  >> 18);
        agg_add(g_hist[1], fkey(vo) >> 18);
    }
}

// ---- P: pick threshold bins. block 0: hist0 -> sel0(top)+sel1(bottom);
//         block 1: hist1 -> sel2(top). ---------------------------------------
__global__ __launch_bounds__(PICK_T)
void pick_kernel(int K) {
    const int hh  = blockIdx.x;
    const int tid = threadIdx.x;
    const unsigned* hist = g_hist[hh];
    __shared__ unsigned s[PICK_T];
    const unsigned uK = (unsigned)K;

    unsigned part = 0;
    #pragma unroll
    for (int j = 0; j < PBPT; j++) part += hist[tid * PBPT + j];
    s[tid] = part;
    __syncthreads();
    for (int off = 1; off < PICK_T; off <<= 1) {    // inclusive scan (ascending)
        unsigned v = (tid >= off) ? s[tid - off] : 0u;
        __syncthreads();
        s[tid] += v;
        __syncthreads();
    }
    unsigned asc   = s[tid];
    unsigned total = s[PICK_T - 1];

    // top-K: descending walk
    {
        unsigned before = total - asc;              // count strictly above my chunk
        if (before < uK && before + part >= uK) {
            int kk = K - (int)before;
            for (int j = PBPT - 1; j >= 0; j--) {
                int b = tid * PBPT + j;
                kk -= (int)hist[b];
                if (kk <= 0) { g_bin[hh == 0 ? 0 : 2] = (unsigned)b; break; }
            }
        }
    }
    // bottom-K (hist0 only): ascending walk
    if (hh == 0) {
        unsigned before = asc - part;
        if (before < uK && asc >= uK) {
            int kk = K - (int)before;
            for (int j = 0; j < PBPT; j++) {
                int b = tid * PBPT + j;
                kk -= (int)hist[b];
                if (kk <= 0) { g_bin[1] = (unsigned)b; break; }
            }
        }
    }
}

// ---- C: warp-aggregated candidate compaction, 1 element/thread --------------
__device__ __forceinline__ void append_warp(int sel, bool pred, unsigned long long key) {
    unsigned m = __ballot_sync(0xFFFFFFFFu, pred);
    if (!m) return;
    int leader = __ffs(m) - 1;
    int lane = threadIdx.x & 31;
    int base = 0;
    if (lane == leader) base = atomicAdd(&g_cnt[sel], __popc(m));
    base = __shfl_sync(0xFFFFFFFFu, base, leader);
    if (pred) {
        int p = base + __popc(m & ((1u << lane) - 1u));
        if (p < CAP) g_cand[sel][p] = key;
    }
}

__global__ __launch_bounds__(256)
void compact_kernel(const float2* __restrict__ A2, const int* __restrict__ bag, int N) {
    const int i = blockIdx.x * 256 + threadIdx.x;
    const int bg = __ldg(bag);
    const unsigned lo0 = g_bin[0];
    const unsigned hi1 = g_bin[1];
    const unsigned lo2 = g_bin[2];

    const bool valid = (i < N);
    float2 a = valid ? A2[i] : make_float2(0.f, 0.f);
    float v  = bg ? a.y : a.x;
    float vo = bg ? a.x : a.y;
    unsigned k0 = fkey(v), k2 = fkey(vo);
    unsigned long long il = (unsigned)(~(unsigned)i);

    append_warp(0, valid && ((k0 >> 18) >= lo0), ((unsigned long long)k0    << 32) | il);
    append_warp(1, valid && ((k0 >> 18) <= hi1), ((unsigned long long)(~k0) << 32) | il);
    append_warp(2, valid && ((k2 >> 18) >= lo2), ((unsigned long long)k2    << 32) | il);
}

// ---- S: per-selection bitonic sort + state zeroing for next replay ----------
__global__ __launch_bounds__(1024)
void sort_kernel(int K) {
    const int sel = blockIdx.x, tid = threadIdx.x;
    __shared__ unsigned long long keys[CAP];

    int cnt = g_cnt[sel]; if (cnt > CAP) cnt = CAP;
    for (int j = tid; j < CAP; j += 1024)
        keys[j] = (j < cnt) ? g_cand[sel][j] : 0ull;
    __syncthreads();

    for (unsigned size = 2; size <= CAP; size <<= 1) {
        for (unsigned stride = size >> 1; stride > 0; stride >>= 1) {
            #pragma unroll 2
            for (int p = tid; p < CAP / 2; p += 1024) {
                unsigned lo = p & (stride - 1);
                unsigned i  = ((unsigned)(p - lo) << 1) | lo;
                unsigned j  = i + stride;
                bool up = ((i & size) == 0);
                unsigned long long a = keys[i], c = keys[j];
                if (up ? (a > c) : (a < c)) { keys[i] = c; keys[j] = a; }
            }
            __syncthreads();
        }
    }

    for (int j = tid; j < K; j += 1024) {
        unsigned long long key = keys[CAP - 1 - j];
        g_idx[sel * K + j] = (int)(~(unsigned)(key & 0xFFFFFFFFull));
    }

    // zero state for next call (each block takes a third of the histograms)
    unsigned* hp = (unsigned*)g_hist;
    const int total = 2 * NBINS;
    const int chunk = (total + 2) / 3;
    const int s0 = sel * chunk;
    const int e0 = (s0 + chunk < total) ? s0 + chunk : total;
    for (int i = s0 + tid; i < e0; i += 1024) hp[i] = 0u;
    if (tid == 0) g_cnt[sel] = 0;
}

// ---- G: gather + GEMV(512->2) + softmax; 2 rows/warp, loads hoisted ---------
__global__ __launch_bounds__(256)
void gemv_softmax_kernel(const float* __restrict__ h,
                         const float* __restrict__ W,
                         const float* __restrict__ b,
                         float* __restrict__ out,
                         int D, int K) {
    extern __shared__ float ws[];   // D*2 floats, W[d*2+c]
    const int tid = threadIdx.x;
    for (int j = tid; j < D * 2; j += blockDim.x) ws[j] = W[j];
    __syncthreads();

    const int warp = tid >> 5, lane = tid & 31;
    const int rbase = (blockIdx.x * (blockDim.x >> 5) + warp) * 2;
    const int total = 3 * K;
    if (rbase >= total) return;

    const bool two = (rbase + 1 < total);
    const int ia = g_idx[rbase];
    const int ib = two ? g_idx[rbase + 1] : ia;
    const float4* pa = (const float4*)(h + (size_t)ia * D);
    const float4* pb = (const float4*)(h + (size_t)ib * D);

    float a0 = 0.f, a1 = 0.f, b0 = 0.f, b1 = 0.f;
    const int nq = D >> 2;

    int t = lane;
    // main: 4 chunks per row per iteration, all 8 loads issued back-to-back (MLP=8)
    for (; t + 96 < nq; t += 128) {
        float4 va0 = pa[t];
        float4 va1 = pa[t + 32];
        float4 va2 = pa[t + 64];
        float4 va3 = pa[t + 96];
        float4 vb0 = pb[t];
        float4 vb1 = pb[t + 32];
        float4 vb2 = pb[t + 64];
        float4 vb3 = pb[t + 96];
        #pragma unroll
        for (int u = 0; u < 4; u++) {
            float4 va = (u == 0) ? va0 : (u == 1) ? va1 : (u == 2) ? va2 : va3;
            float4 vb = (u == 0) ? vb0 : (u == 1) ? vb1 : (u == 2) ? vb2 : vb3;
            int j = (t + u * 32) << 3;
            a0 = fmaf(va.x, ws[j + 0], a0);  a1 = fmaf(va.x, ws[j + 1], a1);
            b0 = fmaf(vb.x, ws[j + 0], b0);  b1 = fmaf(vb.x, ws[j + 1], b1);
            a0 = fmaf(va.y, ws[j + 2], a0);  a1 = fmaf(va.y, ws[j + 3], a1);
            b0 = fmaf(vb.y, ws[j + 2], b0);  b1 = fmaf(vb.y, ws[j + 3], b1);
            a0 = fmaf(va.z, ws[j + 4], a0);  a1 = fmaf(va.z, ws[j + 5], a1);
            b0 = fmaf(vb.z, ws[j + 4], b0);  b1 = fmaf(vb.z, ws[j + 5], b1);
            a0 = fmaf(va.w, ws[j + 6], a0);  a1 = fmaf(va.w, ws[j + 7], a1);
            b0 = fmaf(vb.w, ws[j + 6], b0);  b1 = fmaf(vb.w, ws[j + 7], b1);
        }
    }
    // tail for D not a multiple of 512
    for (; t < nq; t += 32) {
        float4 va = pa[t];
        float4 vb = pb[t];
        int j = t << 3;
        a0 = fmaf(va.x, ws[j + 0], a0);  a1 = fmaf(va.x, ws[j + 1], a1);
        b0 = fmaf(vb.x, ws[j + 0], b0);  b1 = fmaf(vb.x, ws[j + 1], b1);
        a0 = fmaf(va.y, ws[j + 2], a0);  a1 = fmaf(va.y, ws[j + 3], a1);
        b0 = fmaf(vb.y, ws[j + 2], b0);  b1 = fmaf(vb.y, ws[j + 3], b1);
        a0 = fmaf(va.z, ws[j + 4], a0);  a1 = fmaf(va.z, ws[j + 5], a1);
        b0 = fmaf(vb.z, ws[j + 4], b0);  b1 = fmaf(vb.z, ws[j + 5], b1);
        a0 = fmaf(va.w, ws[j + 6], a0);  a1 = fmaf(va.w, ws[j + 7], a1);
        b0 = fmaf(vb.w, ws[j + 6], b0);  b1 = fmaf(vb.w, ws[j + 7], b1);
    }

    #pragma unroll
    for (int o = 16; o; o >>= 1) {
        a0 += __shfl_down_sync(0xFFFFFFFFu, a0, o);
        a1 += __shfl_down_sync(0xFFFFFFFFu, a1, o);
        b0 += __shfl_down_sync(0xFFFFFFFFu, b0, o);
        b1 += __shfl_down_sync(0xFFFFFFFFu, b1, o);
    }

    if (lane == 0) {
        float bb0 = b[0], bb1 = b[1];
        {
            int r = rbase;
            float z0 = a0 + bb0, z1 = a1 + bb1;
            float m = fmaxf(z0, z1);
            float e0 = expf(z0 - m), e1 = expf(z1 - m);
            float inv = 1.0f / (e0 + e1);
            out[r] = (r < K) ? 1.0f : 0.0f;
            out[3 * K + r * 2 + 0] = z0;
            out[3 * K + r * 2 + 1] = z1;
            out[9 * K + r * 2 + 0] = e0 * inv;
            out[9 * K + r * 2 + 1] = e1 * inv;
        }
        if (two) {
            int r = rbase + 1;
            float z0 = b0 + bb0, z1 = b1 + bb1;
            float m = fmaxf(z0, z1);
            float e0 = expf(z0 - m), e1 = expf(z1 - m);
            float inv = 1.0f / (e0 + e1);
            out[r] = (r < K) ? 1.0f : 0.0f;
            out[3 * K + r * 2 + 0] = z0;
            out[3 * K + r * 2 + 1] = z1;
            out[9 * K + r * 2 + 0] = e0 * inv;
            out[9 * K + r * 2 + 1] = e1 * inv;
        }
    }
}

extern "C" void kernel_launch(void* const* d_in, const int* in_sizes, int n_in,
                              void* d_out, int out_size) {
    const float* h = (const float*)d_in[0];   // (N,1,D)
    const float* A = (const float*)d_in[1];   // (N,1,2)
    const float* W = (const float*)d_in[2];   // (D,2)
    const float* b = (const float*)d_in[3];   // (2,)
    const int* bag = (const int*)d_in[4];

    const int N = in_sizes[1] / 2;
    const int D = in_sizes[0] / N;
    int K = (int)(0.02 * (double)N);
    if (K == 0) K = 8;
    if (K > KMAX) K = KMAX;

    const float2* A2 = (const float2*)A;

    hist_kernel<<<256, 256>>>(A2, bag, N);
    pick_kernel<<<2, PICK_T>>>(K);
    compact_kernel<<<(N + 255) / 256, 256>>>(A2, bag, N);
    sort_kernel<<<3, 1024>>>(K);

    const int rows = 3 * K;
    const int blocks = (rows + 15) / 16;      // 8 warps x 2 rows per block
    const size_t smem = (size_t)(D * 2) * sizeof(float);
    gemv_softmax_kernel<<<blocks, 256, smem>>>(h, W, b, (float*)d_out, D, K);
}